// round 1
// baseline (speedup 1.0000x reference)
#include <cuda_runtime.h>

// Problem constants
namespace {
constexpr int B  = 2;
constexpr int S  = 2048;
constexpr int E  = 1024;
constexpr int H  = 16;
constexpr int DH = 64;
constexpr int M  = B * S;    // 4096 rows for projection GEMMs
constexpr int BH = B * H;    // 32 (batch*heads)
constexpr long long OUT_ELEMS = (long long)B * S * E;      // 4194304
constexpr long long W_ELEMS   = (long long)B * H * S * S;  // 134217728
constexpr float ATTN_SCALE = 0.125f;  // 64^-0.5
}

// Scratch (allocation-free rule: __device__ globals)
__device__ float g_qh[(long long)BH * S * DH];   // [B,H,S,DH]
__device__ float g_kh[(long long)BH * S * DH];
__device__ float g_vh[(long long)BH * S * DH];
__device__ float g_att[(long long)M * E];        // [B,S,E] pre-out-projection
__device__ float g_wfallback[W_ELEMS];           // used only if out_size excludes weights

// ---------------------------------------------------------------------------
// Projection GEMM:  out = (X @ W^T + bias) * scale
// X: [M, E] row-major, W: [E(out), E(in)] row-major (torch Linear convention)
// mode 0/1/2: write into g_qh/g_kh/g_vh in [B,H,S,DH] head layout
// mode 3:     write flat [M, E] to outFlat
// Tiling: 64x64 block tile, BK=32, 256 threads, 4x4 per-thread register tile.
// ---------------------------------------------------------------------------
__global__ void __launch_bounds__(256)
proj_kernel(const float* __restrict__ X, const float* __restrict__ Wt,
            const float* __restrict__ bias, float scale,
            int mode, float* __restrict__ outFlat)
{
    __shared__ float As[64][33];
    __shared__ float Bs[64][33];

    const int bm = blockIdx.y * 64;
    const int bn = blockIdx.x * 64;
    const int tid = threadIdx.x;
    const int ty = tid >> 4;
    const int tx = tid & 15;

    float acc[4][4] = {};

    for (int k0 = 0; k0 < E; k0 += 32) {
        #pragma unroll
        for (int i = tid; i < 64 * 32; i += 256) {
            const int r = i >> 5, c = i & 31;
            As[r][c] = X [(long long)(bm + r) * E + k0 + c];
            Bs[r][c] = Wt[(long long)(bn + r) * E + k0 + c];
        }
        __syncthreads();
        #pragma unroll
        for (int c = 0; c < 32; ++c) {
            float a[4], b[4];
            #pragma unroll
            for (int i = 0; i < 4; ++i) a[i] = As[ty * 4 + i][c];
            #pragma unroll
            for (int j = 0; j < 4; ++j) b[j] = Bs[tx * 4 + j][c];
            #pragma unroll
            for (int i = 0; i < 4; ++i)
                #pragma unroll
                for (int j = 0; j < 4; ++j)
                    acc[i][j] = fmaf(a[i], b[j], acc[i][j]);
        }
        __syncthreads();
    }

    float* outHeads = (mode == 0) ? g_qh : (mode == 1) ? g_kh : g_vh;

    #pragma unroll
    for (int i = 0; i < 4; ++i) {
        const int m  = bm + ty * 4 + i;
        const int b_ = m >> 11;          // m / S
        const int s_ = m & (S - 1);
        #pragma unroll
        for (int j = 0; j < 4; ++j) {
            const int n = bn + tx * 4 + j;
            const float v = (acc[i][j] + bias[n]) * scale;
            if (mode == 3) {
                outFlat[(long long)m * E + n] = v;
            } else {
                const int h_ = n >> 6;   // n / DH
                const int d_ = n & 63;
                outHeads[(((long long)(b_ * H + h_)) * S + s_) * DH + d_] = v;
            }
        }
    }
}

// Output projection reads g_att internally (host cannot take its address)
__global__ void __launch_bounds__(256)
outproj_kernel(const float* __restrict__ Wt, const float* __restrict__ bias,
               float* __restrict__ out)
{
    __shared__ float As[64][33];
    __shared__ float Bs[64][33];

    const int bm = blockIdx.y * 64;
    const int bn = blockIdx.x * 64;
    const int tid = threadIdx.x;
    const int ty = tid >> 4;
    const int tx = tid & 15;

    float acc[4][4] = {};

    for (int k0 = 0; k0 < E; k0 += 32) {
        #pragma unroll
        for (int i = tid; i < 64 * 32; i += 256) {
            const int r = i >> 5, c = i & 31;
            As[r][c] = g_att[(long long)(bm + r) * E + k0 + c];
            Bs[r][c] = Wt  [(long long)(bn + r) * E + k0 + c];
        }
        __syncthreads();
        #pragma unroll
        for (int c = 0; c < 32; ++c) {
            float a[4], b[4];
            #pragma unroll
            for (int i = 0; i < 4; ++i) a[i] = As[ty * 4 + i][c];
            #pragma unroll
            for (int j = 0; j < 4; ++j) b[j] = Bs[tx * 4 + j][c];
            #pragma unroll
            for (int i = 0; i < 4; ++i)
                #pragma unroll
                for (int j = 0; j < 4; ++j)
                    acc[i][j] = fmaf(a[i], b[j], acc[i][j]);
        }
        __syncthreads();
    }

    #pragma unroll
    for (int i = 0; i < 4; ++i) {
        const int m = bm + ty * 4 + i;
        #pragma unroll
        for (int j = 0; j < 4; ++j) {
            const int n = bn + tx * 4 + j;
            out[(long long)m * E + n] = acc[i][j] + bias[n];
        }
    }
}

// ---------------------------------------------------------------------------
// Scores: raw[b,h,q,k] = sum_d qh * kh   (q already scaled)
// One block per 64x64 score tile per (b,h). K = DH = 64 in one shot.
// ---------------------------------------------------------------------------
__global__ void __launch_bounds__(256)
scores_kernel(float* __restrict__ outw, int use_fb)
{
    __shared__ float Qs[64][65];
    __shared__ float Ks[64][65];

    float* wts = use_fb ? g_wfallback : outw;

    const int bh = blockIdx.z;
    const int q0 = blockIdx.y * 64;
    const int k0 = blockIdx.x * 64;
    const float* Qb = g_qh + (long long)bh * S * DH;
    const float* Kb = g_kh + (long long)bh * S * DH;
    const int tid = threadIdx.x;

    #pragma unroll
    for (int i = tid; i < 64 * 64; i += 256) {
        const int r = i >> 6, c = i & 63;
        Qs[r][c] = Qb[(q0 + r) * DH + c];
        Ks[r][c] = Kb[(k0 + r) * DH + c];
    }
    __syncthreads();

    const int ty = tid >> 4;
    const int tx = tid & 15;
    float acc[4][4] = {};

    #pragma unroll 16
    for (int c = 0; c < 64; ++c) {
        float a[4], b[4];
        #pragma unroll
        for (int i = 0; i < 4; ++i) a[i] = Qs[ty * 4 + i][c];
        #pragma unroll
        for (int j = 0; j < 4; ++j) b[j] = Ks[tx * 4 + j][c];
        #pragma unroll
        for (int i = 0; i < 4; ++i)
            #pragma unroll
            for (int j = 0; j < 4; ++j)
                acc[i][j] = fmaf(a[i], b[j], acc[i][j]);
    }

    float* Wb = wts + (long long)bh * S * S;
    #pragma unroll
    for (int i = 0; i < 4; ++i)
        #pragma unroll
        for (int j = 0; j < 4; ++j)
            Wb[(long long)(q0 + ty * 4 + i) * S + (k0 + tx * 4 + j)] = acc[i][j];
}

// ---------------------------------------------------------------------------
// Row softmax, in place. One block (256 threads) per row of 2048.
// ---------------------------------------------------------------------------
__global__ void __launch_bounds__(256)
softmax_kernel(float* __restrict__ outw, int use_fb)
{
    float* wts = use_fb ? g_wfallback : outw;
    float* p = wts + (long long)blockIdx.x * S;

    const int tid = threadIdx.x;
    const int lane = tid & 31;
    const int warp = tid >> 5;
    __shared__ float red[32];

    float v[8];
    float mx = -3.4e38f;
    #pragma unroll
    for (int i = 0; i < 8; ++i) {
        v[i] = p[tid + i * 256];
        mx = fmaxf(mx, v[i]);
    }
    #pragma unroll
    for (int o = 16; o; o >>= 1) mx = fmaxf(mx, __shfl_xor_sync(0xffffffffu, mx, o));
    if (lane == 0) red[warp] = mx;
    __syncthreads();
    if (tid < 32) {
        float t = (tid < 8) ? red[tid] : -3.4e38f;
        #pragma unroll
        for (int o = 4; o; o >>= 1) t = fmaxf(t, __shfl_xor_sync(0xffffffffu, t, o));
        red[tid] = t;
    }
    __syncthreads();
    mx = red[0];
    __syncthreads();

    float sum = 0.f;
    #pragma unroll
    for (int i = 0; i < 8; ++i) {
        v[i] = __expf(v[i] - mx);
        sum += v[i];
    }
    #pragma unroll
    for (int o = 16; o; o >>= 1) sum += __shfl_xor_sync(0xffffffffu, sum, o);
    if (lane == 0) red[warp] = sum;
    __syncthreads();
    if (tid < 32) {
        float t = (tid < 8) ? red[tid] : 0.f;
        #pragma unroll
        for (int o = 4; o; o >>= 1) t += __shfl_xor_sync(0xffffffffu, t, o);
        red[tid] = t;
    }
    __syncthreads();
    const float inv = 1.0f / red[0];

    #pragma unroll
    for (int i = 0; i < 8; ++i) p[tid + i * 256] = v[i] * inv;
}

// ---------------------------------------------------------------------------
// PV: att[b,q,h*64+d] = sum_k weights[b,h,q,k] * vh[b,h,k,d]
// 64(q) x 64(d) tile, BK=64, grid (q-tiles, bh).
// ---------------------------------------------------------------------------
__global__ void __launch_bounds__(256)
pv_kernel(const float* __restrict__ outw, int use_fb)
{
    __shared__ float Ws[64][65];
    __shared__ float Vs[64][64];

    const float* wts = use_fb ? g_wfallback : outw;

    const int q0 = blockIdx.x * 64;
    const int bh = blockIdx.y;
    const float* Wb = wts  + (long long)bh * S * S;
    const float* Vb = g_vh + (long long)bh * S * DH;

    const int tid = threadIdx.x;
    const int ty = tid >> 4;
    const int tx = tid & 15;

    float acc[4][4] = {};

    for (int k0 = 0; k0 < S; k0 += 64) {
        #pragma unroll
        for (int i = tid; i < 64 * 64; i += 256) {
            const int r = i >> 6, c = i & 63;
            Ws[r][c] = Wb[(long long)(q0 + r) * S + k0 + c];
            Vs[r][c] = Vb[(k0 + r) * DH + c];
        }
        __syncthreads();
        #pragma unroll 8
        for (int c = 0; c < 64; ++c) {
            float a[4], b[4];
            #pragma unroll
            for (int i = 0; i < 4; ++i) a[i] = Ws[ty * 4 + i][c];
            #pragma unroll
            for (int j = 0; j < 4; ++j) b[j] = Vs[c][tx * 4 + j];
            #pragma unroll
            for (int i = 0; i < 4; ++i)
                #pragma unroll
                for (int j = 0; j < 4; ++j)
                    acc[i][j] = fmaf(a[i], b[j], acc[i][j]);
        }
        __syncthreads();
    }

    const int b_ = bh >> 4;   // bh / H
    const int h_ = bh & 15;
    #pragma unroll
    for (int i = 0; i < 4; ++i) {
        const int q = q0 + ty * 4 + i;
        #pragma unroll
        for (int j = 0; j < 4; ++j) {
            const int d = tx * 4 + j;
            g_att[((long long)(b_ * S + q)) * E + h_ * DH + d] = acc[i][j];
        }
    }
}

// ---------------------------------------------------------------------------
extern "C" void kernel_launch(void* const* d_in, const int* in_sizes, int n_in,
                              void* d_out, int out_size)
{
    const float* q  = (const float*)d_in[0];
    const float* k  = (const float*)d_in[1];
    const float* v  = (const float*)d_in[2];
    const float* Wq = (const float*)d_in[3];
    const float* bq = (const float*)d_in[4];
    const float* Wk = (const float*)d_in[5];
    const float* bk = (const float*)d_in[6];
    const float* Wv = (const float*)d_in[7];
    const float* bv = (const float*)d_in[8];
    const float* Wo = (const float*)d_in[9];
    const float* bo = (const float*)d_in[10];
    float* out = (float*)d_out;

    // If the harness output buffer includes the weights tensor (tuple output),
    // write softmax weights straight into it; otherwise use device scratch.
    const int use_fb = ((long long)out_size < OUT_ELEMS + W_ELEMS) ? 1 : 0;
    float* outw = out + OUT_ELEMS;

    const dim3 blk(256);

    // Projections into head layout [B,H,S,DH]; q gets the 1/sqrt(DH) scale.
    proj_kernel<<<dim3(E / 64, M / 64), blk>>>(q, Wq, bq, ATTN_SCALE, 0, nullptr);
    proj_kernel<<<dim3(E / 64, M / 64), blk>>>(k, Wk, bk, 1.0f,       1, nullptr);
    proj_kernel<<<dim3(E / 64, M / 64), blk>>>(v, Wv, bv, 1.0f,       2, nullptr);

    // Raw scores -> weights buffer
    scores_kernel<<<dim3(S / 64, S / 64, BH), blk>>>(outw, use_fb);

    // Softmax in place
    softmax_kernel<<<dim3(BH * S), blk>>>(outw, use_fb);

    // weights @ V -> g_att [B,S,E]
    pv_kernel<<<dim3(S / 64, BH), blk>>>(outw, use_fb);

    // Output projection -> d_out[0 : B*S*E]
    outproj_kernel<<<dim3(E / 64, M / 64), blk>>>(Wo, bo, out);
}

// round 2
// speedup vs baseline: 2.2851x; 2.2851x over previous
#include <cuda_runtime.h>
#include <mma.h>

using namespace nvcuda;

// Problem constants
namespace {
constexpr int B  = 2;
constexpr int S  = 2048;
constexpr int E  = 1024;
constexpr int H  = 16;
constexpr int DH = 64;
constexpr int M  = B * S;    // 4096
constexpr int BH = B * H;    // 32
constexpr long long OUT_ELEMS = (long long)B * S * E;      // 4194304
constexpr long long W_ELEMS   = (long long)B * H * S * S;  // 134217728
constexpr float ATTN_SCALE = 0.125f;
}

// Scratch (__device__ globals: allocation-free rule)
__device__ float g_qh[(long long)BH * S * DH];   // [B,H,S,DH]
__device__ float g_kh[(long long)BH * S * DH];
__device__ float g_vh[(long long)BH * S * DH];
__device__ float g_att[(long long)M * E];        // [B,S,E]
__device__ float g_wfallback[W_ELEMS];

// ---------------------------------------------------------------------------
// Helpers
// ---------------------------------------------------------------------------
template <typename Frag>
__device__ __forceinline__ void to_tf32(Frag& f) {
    #pragma unroll
    for (int i = 0; i < f.num_elements; ++i)
        f.x[i] = wmma::__float_to_tf32(f.x[i]);
}

// ---------------------------------------------------------------------------
// Unified projection GEMM: out = (X @ Wt^T + bias) * scale
// X:[M,E] rm, Wt:[N,K]=[E,E] rm (torch Linear). Block 128x128, BK=32,
// 8 warps in 2x4, warp tile 64x32 (4x2 wmma 16x16x8 tf32 frags).
// mode 0/1/2 -> scatter into g_qh/g_kh/g_vh head layout; mode 3 -> flat out.
// ---------------------------------------------------------------------------
__global__ void __launch_bounds__(256)
gemm_tf32_kernel(const float* __restrict__ Ain, const float* __restrict__ Wt,
                 const float* __restrict__ bias, float scale,
                 int mode, float* __restrict__ outFlat)
{
    __shared__ __align__(16) float As[128][36];
    __shared__ __align__(16) float Bs[128][36];
    __shared__ __align__(16) float scr[8][16 * 20];

    const float* Aeff = (mode == 3) ? g_att : Ain;

    const int bm = blockIdx.y * 128;
    const int bn = blockIdx.x * 128;
    const int tid  = threadIdx.x;
    const int warp = tid >> 5;
    const int lane = tid & 31;
    const int warpM = warp >> 2;   // 0..1
    const int warpN = warp & 3;    // 0..3

    wmma::fragment<wmma::accumulator, 16, 16, 8, float> c[4][2];
    #pragma unroll
    for (int mi = 0; mi < 4; ++mi)
        #pragma unroll
        for (int ni = 0; ni < 2; ++ni)
            wmma::fill_fragment(c[mi][ni], 0.0f);

    for (int k0 = 0; k0 < E; k0 += 32) {
        #pragma unroll
        for (int i = tid; i < 128 * 8; i += 256) {
            const int r = i >> 3, c4 = i & 7;
            *(float4*)&As[r][c4 * 4] =
                *(const float4*)&Aeff[(size_t)(bm + r) * E + k0 + c4 * 4];
            *(float4*)&Bs[r][c4 * 4] =
                *(const float4*)&Wt[(size_t)(bn + r) * E + k0 + c4 * 4];
        }
        __syncthreads();

        #pragma unroll
        for (int kc = 0; kc < 4; ++kc) {
            wmma::fragment<wmma::matrix_a, 16, 16, 8, wmma::precision::tf32, wmma::row_major> a[4];
            wmma::fragment<wmma::matrix_b, 16, 16, 8, wmma::precision::tf32, wmma::col_major> b[2];
            #pragma unroll
            for (int mi = 0; mi < 4; ++mi) {
                wmma::load_matrix_sync(a[mi], &As[warpM * 64 + mi * 16][kc * 8], 36);
                to_tf32(a[mi]);
            }
            #pragma unroll
            for (int ni = 0; ni < 2; ++ni) {
                wmma::load_matrix_sync(b[ni], &Bs[warpN * 32 + ni * 16][kc * 8], 36);
                to_tf32(b[ni]);
            }
            #pragma unroll
            for (int mi = 0; mi < 4; ++mi)
                #pragma unroll
                for (int ni = 0; ni < 2; ++ni)
                    wmma::mma_sync(c[mi][ni], a[mi], b[ni], c[mi][ni]);
        }
        __syncthreads();
    }

    float* outHeads = (mode == 0) ? g_qh : (mode == 1) ? g_kh : g_vh;

    #pragma unroll
    for (int mi = 0; mi < 4; ++mi) {
        #pragma unroll
        for (int ni = 0; ni < 2; ++ni) {
            wmma::store_matrix_sync(&scr[warp][0], c[mi][ni], 20, wmma::mem_row_major);
            __syncwarp();
            const int m0 = bm + warpM * 64 + mi * 16;
            const int n0 = bn + warpN * 32 + ni * 16;
            #pragma unroll
            for (int it = 0; it < 8; ++it) {
                const int idx = lane + it * 32;
                const int r = idx >> 4, cc = idx & 15;
                const int m = m0 + r;
                const int n = n0 + cc;
                const float v = (scr[warp][r * 20 + cc] + bias[n]) * scale;
                if (mode == 3) {
                    outFlat[(size_t)m * E + n] = v;
                } else {
                    const int b_ = m >> 11, s_ = m & (S - 1);
                    const int h_ = n >> 6,  d_ = n & 63;
                    outHeads[(((size_t)(b_ * H + h_)) * S + s_) * DH + d_] = v;
                }
            }
            __syncwarp();
        }
    }
}

// ---------------------------------------------------------------------------
// Scores: raw[bh,q,k] = sum_d qh[q,d] * kh[k,d]  (q pre-scaled)
// Block tile 128q x 128k, DH=64 split into two 32-chunks in smem.
// ---------------------------------------------------------------------------
__global__ void __launch_bounds__(256)
scores_tf32_kernel(float* __restrict__ outw, int use_fb)
{
    __shared__ __align__(16) float Qs[128][36];
    __shared__ __align__(16) float Ks[128][36];

    float* wts = use_fb ? g_wfallback : outw;

    const int bh = blockIdx.z;
    const int q0 = blockIdx.y * 128;
    const int k0 = blockIdx.x * 128;
    const float* Qb = g_qh + (size_t)bh * S * DH;
    const float* Kb = g_kh + (size_t)bh * S * DH;

    const int tid  = threadIdx.x;
    const int warp = tid >> 5;
    const int warpM = warp >> 2;
    const int warpN = warp & 3;

    wmma::fragment<wmma::accumulator, 16, 16, 8, float> c[4][2];
    #pragma unroll
    for (int mi = 0; mi < 4; ++mi)
        #pragma unroll
        for (int ni = 0; ni < 2; ++ni)
            wmma::fill_fragment(c[mi][ni], 0.0f);

    #pragma unroll
    for (int kd = 0; kd < DH; kd += 32) {
        #pragma unroll
        for (int i = tid; i < 128 * 8; i += 256) {
            const int r = i >> 3, c4 = i & 7;
            *(float4*)&Qs[r][c4 * 4] =
                *(const float4*)&Qb[(size_t)(q0 + r) * DH + kd + c4 * 4];
            *(float4*)&Ks[r][c4 * 4] =
                *(const float4*)&Kb[(size_t)(k0 + r) * DH + kd + c4 * 4];
        }
        __syncthreads();

        #pragma unroll
        for (int kc = 0; kc < 4; ++kc) {
            wmma::fragment<wmma::matrix_a, 16, 16, 8, wmma::precision::tf32, wmma::row_major> a[4];
            wmma::fragment<wmma::matrix_b, 16, 16, 8, wmma::precision::tf32, wmma::col_major> b[2];
            #pragma unroll
            for (int mi = 0; mi < 4; ++mi) {
                wmma::load_matrix_sync(a[mi], &Qs[warpM * 64 + mi * 16][kc * 8], 36);
                to_tf32(a[mi]);
            }
            #pragma unroll
            for (int ni = 0; ni < 2; ++ni) {
                wmma::load_matrix_sync(b[ni], &Ks[warpN * 32 + ni * 16][kc * 8], 36);
                to_tf32(b[ni]);
            }
            #pragma unroll
            for (int mi = 0; mi < 4; ++mi)
                #pragma unroll
                for (int ni = 0; ni < 2; ++ni)
                    wmma::mma_sync(c[mi][ni], a[mi], b[ni], c[mi][ni]);
        }
        __syncthreads();
    }

    float* Wb = wts + (size_t)bh * S * S;
    #pragma unroll
    for (int mi = 0; mi < 4; ++mi)
        #pragma unroll
        for (int ni = 0; ni < 2; ++ni)
            wmma::store_matrix_sync(
                &Wb[(size_t)(q0 + warpM * 64 + mi * 16) * S + k0 + warpN * 32 + ni * 16],
                c[mi][ni], S, wmma::mem_row_major);
}

// ---------------------------------------------------------------------------
// Row softmax in place. One block (256 threads) per row of 2048.
// ---------------------------------------------------------------------------
__global__ void __launch_bounds__(256)
softmax_kernel(float* __restrict__ outw, int use_fb)
{
    float* wts = use_fb ? g_wfallback : outw;
    float* p = wts + (size_t)blockIdx.x * S;

    const int tid = threadIdx.x;
    const int lane = tid & 31;
    const int warp = tid >> 5;
    __shared__ float red[32];

    float v[8];
    float mx = -3.4e38f;
    #pragma unroll
    for (int i = 0; i < 8; ++i) {
        v[i] = p[tid + i * 256];
        mx = fmaxf(mx, v[i]);
    }
    #pragma unroll
    for (int o = 16; o; o >>= 1) mx = fmaxf(mx, __shfl_xor_sync(0xffffffffu, mx, o));
    if (lane == 0) red[warp] = mx;
    __syncthreads();
    if (tid < 32) {
        float t = (tid < 8) ? red[tid] : -3.4e38f;
        #pragma unroll
        for (int o = 4; o; o >>= 1) t = fmaxf(t, __shfl_xor_sync(0xffffffffu, t, o));
        red[tid] = t;
    }
    __syncthreads();
    mx = red[0];
    __syncthreads();

    float sum = 0.f;
    #pragma unroll
    for (int i = 0; i < 8; ++i) {
        v[i] = __expf(v[i] - mx);
        sum += v[i];
    }
    #pragma unroll
    for (int o = 16; o; o >>= 1) sum += __shfl_xor_sync(0xffffffffu, sum, o);
    if (lane == 0) red[warp] = sum;
    __syncthreads();
    if (tid < 32) {
        float t = (tid < 8) ? red[tid] : 0.f;
        #pragma unroll
        for (int o = 4; o; o >>= 1) t += __shfl_xor_sync(0xffffffffu, t, o);
        red[tid] = t;
    }
    __syncthreads();
    const float inv = 1.0f / red[0];

    #pragma unroll
    for (int i = 0; i < 8; ++i) p[tid + i * 256] = v[i] * inv;
}

// ---------------------------------------------------------------------------
// PV: att[b,q,h*64+d] = sum_k w[bh,q,k] * vh[bh,k,d]
// Block tile 128q x 64d, BK=32. V transposed into smem (Vt[d][k]) so the
// wmma B operand is col-major.
// ---------------------------------------------------------------------------
__global__ void __launch_bounds__(256)
pv_tf32_kernel(const float* __restrict__ outw, int use_fb)
{
    __shared__ __align__(16) float Ws[128][36];
    __shared__ __align__(16) float Vt[64][36];

    const float* wts = use_fb ? g_wfallback : outw;

    const int q0 = blockIdx.x * 128;
    const int bh = blockIdx.y;
    const float* Wb = wts  + (size_t)bh * S * S;
    const float* Vb = g_vh + (size_t)bh * S * DH;

    const int tid  = threadIdx.x;
    const int warp = tid >> 5;
    const int warpM = warp >> 2;   // 0..1
    const int warpN = warp & 3;    // 0..3 -> 16-wide d slice

    wmma::fragment<wmma::accumulator, 16, 16, 8, float> c[4];
    #pragma unroll
    for (int mi = 0; mi < 4; ++mi) wmma::fill_fragment(c[mi], 0.0f);

    for (int k0 = 0; k0 < S; k0 += 32) {
        #pragma unroll
        for (int i = tid; i < 128 * 8; i += 256) {
            const int r = i >> 3, c4 = i & 7;
            *(float4*)&Ws[r][c4 * 4] =
                *(const float4*)&Wb[(size_t)(q0 + r) * S + k0 + c4 * 4];
        }
        #pragma unroll
        for (int i = tid; i < 32 * 64; i += 256) {
            const int k = i >> 6, d = i & 63;
            Vt[d][k] = Vb[(size_t)(k0 + k) * DH + d];
        }
        __syncthreads();

        #pragma unroll
        for (int kc = 0; kc < 4; ++kc) {
            wmma::fragment<wmma::matrix_a, 16, 16, 8, wmma::precision::tf32, wmma::row_major> a[4];
            wmma::fragment<wmma::matrix_b, 16, 16, 8, wmma::precision::tf32, wmma::col_major> b;
            #pragma unroll
            for (int mi = 0; mi < 4; ++mi) {
                wmma::load_matrix_sync(a[mi], &Ws[warpM * 64 + mi * 16][kc * 8], 36);
                to_tf32(a[mi]);
            }
            wmma::load_matrix_sync(b, &Vt[warpN * 16][kc * 8], 36);
            to_tf32(b);
            #pragma unroll
            for (int mi = 0; mi < 4; ++mi)
                wmma::mma_sync(c[mi], a[mi], b, c[mi]);
        }
        __syncthreads();
    }

    const int b_ = bh >> 4, h_ = bh & 15;
    #pragma unroll
    for (int mi = 0; mi < 4; ++mi)
        wmma::store_matrix_sync(
            &g_att[((size_t)(b_ * S + q0 + warpM * 64 + mi * 16)) * E + h_ * DH + warpN * 16],
            c[mi], E, wmma::mem_row_major);
}

// ---------------------------------------------------------------------------
extern "C" void kernel_launch(void* const* d_in, const int* in_sizes, int n_in,
                              void* d_out, int out_size)
{
    const float* q  = (const float*)d_in[0];
    const float* k  = (const float*)d_in[1];
    const float* v  = (const float*)d_in[2];
    const float* Wq = (const float*)d_in[3];
    const float* bq = (const float*)d_in[4];
    const float* Wk = (const float*)d_in[5];
    const float* bk = (const float*)d_in[6];
    const float* Wv = (const float*)d_in[7];
    const float* bv = (const float*)d_in[8];
    const float* Wo = (const float*)d_in[9];
    const float* bo = (const float*)d_in[10];
    float* out = (float*)d_out;

    const int use_fb = ((long long)out_size < OUT_ELEMS + W_ELEMS) ? 1 : 0;
    float* outw = out + OUT_ELEMS;

    const dim3 blk(256);
    const dim3 gemm_grid(E / 128, M / 128);   // (8, 32)

    gemm_tf32_kernel<<<gemm_grid, blk>>>(q, Wq, bq, ATTN_SCALE, 0, nullptr);
    gemm_tf32_kernel<<<gemm_grid, blk>>>(k, Wk, bk, 1.0f,       1, nullptr);
    gemm_tf32_kernel<<<gemm_grid, blk>>>(v, Wv, bv, 1.0f,       2, nullptr);

    scores_tf32_kernel<<<dim3(S / 128, S / 128, BH), blk>>>(outw, use_fb);

    softmax_kernel<<<dim3(BH * S), blk>>>(outw, use_fb);

    pv_tf32_kernel<<<dim3(S / 128, BH), blk>>>(outw, use_fb);

    gemm_tf32_kernel<<<gemm_grid, blk>>>(nullptr, Wo, bo, 1.0f, 3, out);
}